// round 1
// baseline (speedup 1.0000x reference)
#include <cuda_runtime.h>

// Problem constants (fixed by the reference: B=4, N=4096, C=256)
#define BB 4
#define NN 4096
#define CC 256
#define M_TOT (BB * NN)          // 16384 rows
#define LN_EPS 1e-6f
#define STAT_CHUNKS 8            // row-chunks per batch for the column reduction
#define CHUNK_ROWS (NN / STAT_CHUNKS)  // 512

// ---------------------------------------------------------------------------
// Scratch (static device globals; no runtime allocation allowed)
// ---------------------------------------------------------------------------
__device__ float g_Wvo[CC * CC];                 // Wv @ Wo
__device__ float g_bfull[CC];                    // bv @ Wo + bo
__device__ float g_z[(size_t)M_TOT * CC];        // pre-LN activations (64 MB)
__device__ float g_psum[BB * STAT_CHUNKS * CC];  // partial column sums
__device__ float g_psq[BB * STAT_CHUNKS * CC];   // partial column sum-squares
__device__ float g_mean[BB * CC];
__device__ float g_inv[BB * CC];                 // rsqrt(var + eps)

// ---------------------------------------------------------------------------
// Kernel 1: fold weights.  Wvo = Wv @ Wo ; bfull = bv @ Wo + bo
// grid(256) x block(256): block i = output row, thread j = output col.
// ---------------------------------------------------------------------------
__global__ void k_prep(const float* __restrict__ Wv, const float* __restrict__ Wo,
                       const float* __restrict__ bv, const float* __restrict__ bo) {
    const int i = blockIdx.x;
    const int j = threadIdx.x;
    float acc = 0.f;
#pragma unroll 8
    for (int k = 0; k < CC; ++k)
        acc += Wv[i * CC + k] * Wo[k * CC + j];
    g_Wvo[i * CC + j] = acc;
    if (i == 0) {
        float b = 0.f;
#pragma unroll 8
        for (int k = 0; k < CC; ++k)
            b += bv[k] * Wo[k * CC + j];
        g_bfull[j] = b + bo[j];
    }
}

// ---------------------------------------------------------------------------
// Kernel 2: SGEMM  z = X[16384,256] @ Wvo[256,256] + bfull
// 128x128 tile, BK=8, 256 threads, 8x8 per-thread microtile.
// ---------------------------------------------------------------------------
__global__ void __launch_bounds__(256)
k_gemm(const float* __restrict__ X) {
    __shared__ float As[8][128];   // transposed A tile: [k][m]
    __shared__ float Bs[8][128];   // B tile: [k][n]

    const int tid     = threadIdx.x;
    const int rowBase = blockIdx.y * 128;
    const int colBase = blockIdx.x * 128;

    // A-load mapping: 128 rows x 8 k -> 4 floats/thread (float4 along k)
    const int a_row = tid >> 1;            // 0..127
    const int a_col = (tid & 1) << 2;      // 0 or 4
    // B-load mapping: 8 k x 128 n -> float4 along n
    const int b_row = tid >> 5;            // 0..7
    const int b_col = (tid & 31) << 2;     // 0..124

    const int ty = tid >> 4;               // 0..15 -> row group
    const int tx = tid & 15;               // 0..15 -> col group

    float acc[8][8];
#pragma unroll
    for (int i = 0; i < 8; ++i)
#pragma unroll
        for (int j = 0; j < 8; ++j) acc[i][j] = 0.f;

    for (int k0 = 0; k0 < CC; k0 += 8) {
        float4 av = *(const float4*)(X + (size_t)(rowBase + a_row) * CC + k0 + a_col);
        As[a_col + 0][a_row] = av.x;
        As[a_col + 1][a_row] = av.y;
        As[a_col + 2][a_row] = av.z;
        As[a_col + 3][a_row] = av.w;
        *(float4*)&Bs[b_row][b_col] =
            *(const float4*)(g_Wvo + (k0 + b_row) * CC + colBase + b_col);
        __syncthreads();

#pragma unroll
        for (int kk = 0; kk < 8; ++kk) {
            float4 a0 = *(const float4*)&As[kk][ty * 8];
            float4 a1 = *(const float4*)&As[kk][ty * 8 + 4];
            float4 b0 = *(const float4*)&Bs[kk][tx * 8];
            float4 b1 = *(const float4*)&Bs[kk][tx * 8 + 4];
            float a[8] = {a0.x, a0.y, a0.z, a0.w, a1.x, a1.y, a1.z, a1.w};
            float b[8] = {b0.x, b0.y, b0.z, b0.w, b1.x, b1.y, b1.z, b1.w};
#pragma unroll
            for (int i = 0; i < 8; ++i)
#pragma unroll
                for (int j = 0; j < 8; ++j)
                    acc[i][j] += a[i] * b[j];
        }
        __syncthreads();
    }

    // Store with fused bias
#pragma unroll
    for (int i = 0; i < 8; ++i) {
        const int r = rowBase + ty * 8 + i;
#pragma unroll
        for (int j = 0; j < 8; j += 4) {
            const int c = colBase + tx * 8 + j;
            float4 bf = *(const float4*)(g_bfull + c);
            float4 o;
            o.x = acc[i][j + 0] + bf.x;
            o.y = acc[i][j + 1] + bf.y;
            o.z = acc[i][j + 2] + bf.z;
            o.w = acc[i][j + 3] + bf.w;
            *(float4*)(g_z + (size_t)r * CC + c) = o;
        }
    }
}

// ---------------------------------------------------------------------------
// Kernel 3: partial column stats over the points axis (deterministic, no atomics)
// grid(STAT_CHUNKS, BB) x block(256); thread = channel.
// ---------------------------------------------------------------------------
__global__ void k_stats() {
    const int b     = blockIdx.y;
    const int chunk = blockIdx.x;
    const int c     = threadIdx.x;
    const float* zp = g_z + ((size_t)b * NN + (size_t)chunk * CHUNK_ROWS) * CC + c;
    float s = 0.f, s2 = 0.f;
#pragma unroll 4
    for (int r = 0; r < CHUNK_ROWS; ++r) {
        float v = zp[(size_t)r * CC];
        s  += v;
        s2 += v * v;
    }
    g_psum[(b * STAT_CHUNKS + chunk) * CC + c] = s;
    g_psq [(b * STAT_CHUNKS + chunk) * CC + c] = s2;
}

// ---------------------------------------------------------------------------
// Kernel 4: finalize mean / inv-std per (batch, channel)
// grid(BB) x block(256)
// ---------------------------------------------------------------------------
__global__ void k_finalize() {
    const int b = blockIdx.x;
    const int c = threadIdx.x;
    float s = 0.f, s2 = 0.f;
#pragma unroll
    for (int ch = 0; ch < STAT_CHUNKS; ++ch) {
        s  += g_psum[(b * STAT_CHUNKS + ch) * CC + c];
        s2 += g_psq [(b * STAT_CHUNKS + ch) * CC + c];
    }
    const float mean = s * (1.f / NN);
    const float var  = s2 * (1.f / NN) - mean * mean;
    g_mean[b * CC + c] = mean;
    g_inv [b * CC + c] = rsqrtf(var + LN_EPS);
}

// ---------------------------------------------------------------------------
// Kernel 5: epilogue  out = relu((z-mean)*inv*scale + bias) + x
// float4-vectorized; grid(4096) x block(256)
// ---------------------------------------------------------------------------
__global__ void __launch_bounds__(256)
k_epi(const float* __restrict__ X, const float* __restrict__ scale,
      const float* __restrict__ bias, float* __restrict__ out) {
    const int idx = blockIdx.x * blockDim.x + threadIdx.x;   // float4 index
    const int c4  = idx & 63;          // float4 column (256/4 per row)
    const int row = idx >> 6;          // global row
    const int b   = row >> 12;         // 4096 rows per batch

    float4 z  = ((const float4*)g_z)[idx];
    float4 x  = ((const float4*)X)[idx];
    float4 mn = ((const float4*)(g_mean + b * CC))[c4];
    float4 iv = ((const float4*)(g_inv  + b * CC))[c4];
    float4 sc = ((const float4*)scale)[c4];
    float4 bi = ((const float4*)bias)[c4];

    float4 o;
    o.x = fmaxf((z.x - mn.x) * iv.x * sc.x + bi.x, 0.f) + x.x;
    o.y = fmaxf((z.y - mn.y) * iv.y * sc.y + bi.y, 0.f) + x.y;
    o.z = fmaxf((z.z - mn.z) * iv.z * sc.z + bi.z, 0.f) + x.z;
    o.w = fmaxf((z.w - mn.w) * iv.w * sc.w + bi.w, 0.f) + x.w;
    ((float4*)out)[idx] = o;
}

// ---------------------------------------------------------------------------
// Input order (metadata): 0=inputs 1=mask 2=Wq 3=bq 4=Wk 5=bk 6=Wv 7=bv
//                         8=Wo 9=bo 10=ln_scale 11=ln_bias
// mask/Wq/bq/Wk/bk are numerically irrelevant (see analysis) and unused.
// ---------------------------------------------------------------------------
extern "C" void kernel_launch(void* const* d_in, const int* in_sizes, int n_in,
                              void* d_out, int out_size) {
    const float* x        = (const float*)d_in[0];
    const float* Wv       = (const float*)d_in[6];
    const float* bv       = (const float*)d_in[7];
    const float* Wo       = (const float*)d_in[8];
    const float* bo       = (const float*)d_in[9];
    const float* ln_scale = (const float*)d_in[10];
    const float* ln_bias  = (const float*)d_in[11];
    float* out = (float*)d_out;

    k_prep<<<CC, CC>>>(Wv, Wo, bv, bo);
    k_gemm<<<dim3(CC / 128, M_TOT / 128), 256>>>(x);
    k_stats<<<dim3(STAT_CHUNKS, BB), CC>>>();
    k_finalize<<<BB, CC>>>();
    k_epi<<<(M_TOT * CC / 4) / 256, 256>>>(x, ln_scale, ln_bias, out);
}

// round 2
// speedup vs baseline: 1.1474x; 1.1474x over previous
#include <cuda_runtime.h>
#include <cstring>

// Problem constants (fixed by the reference: B=4, N=4096, C=256)
#define BB 4
#define NN 4096
#define CC 256
#define M_TOT (BB * NN)          // 16384 rows
#define LN_EPS 1e-6f
#define CHUNKS_PER_B 32          // 4096 / 128 row-chunks per batch

// ---------------------------------------------------------------------------
// Scratch (static device globals; no runtime allocation allowed)
// ---------------------------------------------------------------------------
__device__ float g_Wvo[CC * CC];                 // Wv @ Wo  (biases cancel in LN)
__device__ float g_z[(size_t)M_TOT * CC];        // pre-LN activations (64 MB)
__device__ float g_psum[(M_TOT / 128) * CC];     // per-128-row-chunk column sums
__device__ float g_psq [(M_TOT / 128) * CC];     // per-chunk column sum-squares
__device__ float g_mean[BB * CC];
__device__ float g_inv[BB * CC];                 // rsqrt(var + eps)

// ---------------------------------------------------------------------------
// Kernel 1: fold weights.  Wvo = Wv @ Wo.
// (bv@Wo + bo shifts each column by a constant -> cancels exactly in LayerNorm
//  over the points axis; biases are dead.)
// ---------------------------------------------------------------------------
__global__ void k_prep(const float* __restrict__ Wv, const float* __restrict__ Wo) {
    const int i = blockIdx.x;
    const int j = threadIdx.x;
    float acc = 0.f;
#pragma unroll 8
    for (int k = 0; k < CC; ++k)
        acc += Wv[i * CC + k] * Wo[k * CC + j];
    g_Wvo[i * CC + j] = acc;
}

// ---------------------------------------------------------------------------
// Kernel 2: SGEMM z = X[16384,256] @ Wvo  (packed f32x2 FMA, 2x FFMA rate)
// + fused per-block column stats (sum / sumsq over the block's 128 rows).
// 128x128 tile, BK=8, 256 threads, 8x8 per-thread microtile as 8x4 f32x2.
// A is stored DUPLICATED in smem ({a,a} per element) so one LDS.64 yields a
// packed broadcast operand; B float4 halves are natural {b_j, b_j+1} pairs.
// ---------------------------------------------------------------------------
__global__ void __launch_bounds__(256)
k_gemm(const float* __restrict__ X) {
    __shared__ float2 As2[8][128];          // duplicated A tile: [k][m] -> {a,a}
    __shared__ float  Bs[8][128];           // B tile: [k][n]
    __shared__ float  red[2][16][128];      // stats reduction (sum, sumsq)

    const int tid     = threadIdx.x;
    const int rowBase = blockIdx.y * 128;
    const int colBase = blockIdx.x * 128;

    const int a_row = tid >> 1;             // 0..127
    const int a_col = (tid & 1) << 2;       // 0 or 4
    const int b_row = tid >> 5;             // 0..7
    const int b_col = (tid & 31) << 2;      // 0..124

    const int ty = tid >> 4;                // 0..15 row group
    const int tx = tid & 15;                // 0..15 col group

    __align__(16) unsigned long long acc2[8][4];   // 8 rows x 4 f32x2 pairs
#pragma unroll
    for (int i = 0; i < 8; ++i)
#pragma unroll
        for (int p = 0; p < 4; ++p) acc2[i][p] = 0ull;

    for (int k0 = 0; k0 < CC; k0 += 8) {
        float4 av = *(const float4*)(X + (size_t)(rowBase + a_row) * CC + k0 + a_col);
        As2[a_col + 0][a_row] = make_float2(av.x, av.x);
        As2[a_col + 1][a_row] = make_float2(av.y, av.y);
        As2[a_col + 2][a_row] = make_float2(av.z, av.z);
        As2[a_col + 3][a_row] = make_float2(av.w, av.w);
        *(float4*)&Bs[b_row][b_col] =
            *(const float4*)(g_Wvo + (k0 + b_row) * CC + colBase + b_col);
        __syncthreads();

#pragma unroll
        for (int kk = 0; kk < 8; ++kk) {
            unsigned long long a2[8], b2[4];
#pragma unroll
            for (int i = 0; i < 8; ++i)
                a2[i] = *(const unsigned long long*)&As2[kk][ty * 8 + i];
#pragma unroll
            for (int p = 0; p < 4; ++p)
                b2[p] = *(const unsigned long long*)&Bs[kk][tx * 8 + 2 * p];
#pragma unroll
            for (int i = 0; i < 8; ++i)
#pragma unroll
                for (int p = 0; p < 4; ++p)
                    asm("fma.rn.f32x2 %0, %1, %2, %0;"
                        : "+l"(acc2[i][p]) : "l"(a2[i]), "l"(b2[p]));
        }
        __syncthreads();
    }

    // ---- store z (no bias) + accumulate thread-local column stats ----
    float s[8], s2[8];
#pragma unroll
    for (int j = 0; j < 8; ++j) { s[j] = 0.f; s2[j] = 0.f; }

#pragma unroll
    for (int i = 0; i < 8; ++i) {
        const int r = rowBase + ty * 8 + i;
        float* zp = g_z + (size_t)r * CC + colBase + tx * 8;
        *(float4*)(zp)     = *(const float4*)&acc2[i][0];
        *(float4*)(zp + 4) = *(const float4*)&acc2[i][2];
#pragma unroll
        for (int p = 0; p < 4; ++p) {
            float2 v;
            memcpy(&v, &acc2[i][p], 8);
            s [2 * p]     += v.x;  s [2 * p + 1] += v.y;
            s2[2 * p]     += v.x * v.x;
            s2[2 * p + 1] += v.y * v.y;
        }
    }

    // ---- deterministic cross-ty tree reduction of column stats ----
#pragma unroll
    for (int j = 0; j < 8; ++j) {
        red[0][ty][tx * 8 + j] = s[j];
        red[1][ty][tx * 8 + j] = s2[j];
    }
    __syncthreads();
#pragma unroll
    for (int st = 8; st > 0; st >>= 1) {
        if (ty < st) {
#pragma unroll
            for (int j = 0; j < 8; ++j) {
                red[0][ty][tx * 8 + j] += red[0][ty + st][tx * 8 + j];
                red[1][ty][tx * 8 + j] += red[1][ty + st][tx * 8 + j];
            }
        }
        __syncthreads();
    }
    if (ty == 0) {
        float* ps = g_psum + blockIdx.y * CC + colBase + tx * 8;
        float* pq = g_psq  + blockIdx.y * CC + colBase + tx * 8;
#pragma unroll
        for (int j = 0; j < 8; ++j) {
            ps[j] = red[0][0][tx * 8 + j];
            pq[j] = red[1][0][tx * 8 + j];
        }
    }
}

// ---------------------------------------------------------------------------
// Kernel 3: finalize mean / inv-std per (batch, channel) from 32 chunk partials
// ---------------------------------------------------------------------------
__global__ void k_finalize() {
    const int b = blockIdx.x;
    const int c = threadIdx.x;
    float s = 0.f, s2 = 0.f;
#pragma unroll
    for (int ch = 0; ch < CHUNKS_PER_B; ++ch) {
        s  += g_psum[(b * CHUNKS_PER_B + ch) * CC + c];
        s2 += g_psq [(b * CHUNKS_PER_B + ch) * CC + c];
    }
    const float mean = s * (1.f / NN);
    const float var  = s2 * (1.f / NN) - mean * mean;
    g_mean[b * CC + c] = mean;
    g_inv [b * CC + c] = rsqrtf(var + LN_EPS);
}

// ---------------------------------------------------------------------------
// Kernel 4: epilogue  out = relu((z-mean)*inv*scale + bias) + x
// ---------------------------------------------------------------------------
__global__ void __launch_bounds__(256)
k_epi(const float* __restrict__ X, const float* __restrict__ scale,
      const float* __restrict__ bias, float* __restrict__ out) {
    const int idx = blockIdx.x * blockDim.x + threadIdx.x;   // float4 index
    const int c4  = idx & 63;
    const int row = idx >> 6;
    const int b   = row >> 12;

    float4 z  = ((const float4*)g_z)[idx];
    float4 x  = ((const float4*)X)[idx];
    float4 mn = ((const float4*)(g_mean + b * CC))[c4];
    float4 iv = ((const float4*)(g_inv  + b * CC))[c4];
    float4 sc = ((const float4*)scale)[c4];
    float4 bi = ((const float4*)bias)[c4];

    float4 o;
    o.x = fmaxf((z.x - mn.x) * iv.x * sc.x + bi.x, 0.f) + x.x;
    o.y = fmaxf((z.y - mn.y) * iv.y * sc.y + bi.y, 0.f) + x.y;
    o.z = fmaxf((z.z - mn.z) * iv.z * sc.z + bi.z, 0.f) + x.z;
    o.w = fmaxf((z.w - mn.w) * iv.w * sc.w + bi.w, 0.f) + x.w;
    ((float4*)out)[idx] = o;
}

// ---------------------------------------------------------------------------
// Inputs: 0=inputs 1=mask 2=Wq 3=bq 4=Wk 5=bk 6=Wv 7=bv 8=Wo 9=bo
//         10=ln_scale 11=ln_bias
// mask/Wq/bq/Wk/bk numerically irrelevant (softmax column-sum collapse);
// bv/bo cancel in the points-axis LayerNorm. All dead.
// ---------------------------------------------------------------------------
extern "C" void kernel_launch(void* const* d_in, const int* in_sizes, int n_in,
                              void* d_out, int out_size) {
    const float* x        = (const float*)d_in[0];
    const float* Wv       = (const float*)d_in[6];
    const float* Wo       = (const float*)d_in[8];
    const float* ln_scale = (const float*)d_in[10];
    const float* ln_bias  = (const float*)d_in[11];
    float* out = (float*)d_out;

    k_prep<<<CC, CC>>>(Wv, Wo);
    k_gemm<<<dim3(CC / 128, M_TOT / 128), 256>>>(x);
    k_finalize<<<BB, CC>>>();
    k_epi<<<(M_TOT * CC / 4) / 256, 256>>>(x, ln_scale, ln_bias, out);
}

// round 4
// speedup vs baseline: 2.0893x; 1.8209x over previous
#include <cuda_runtime.h>
#include <cuda_bf16.h>
#include <cstdint>

// Problem constants (fixed by the reference: B=4, N=4096, C=256)
#define BB 4
#define NN 4096
#define CC 256
#define M_TOT (BB * NN)          // 16384 rows
#define LN_EPS 1e-6f

// ---------------------------------------------------------------------------
// Scratch (static device globals; no runtime allocation allowed)
// ---------------------------------------------------------------------------
__device__ __align__(16) __nv_bfloat16 g_BhT[CC * CC]; // [n][k] = hi(Wvo[k][n])
__device__ __align__(16) __nv_bfloat16 g_BlT[CC * CC]; // [n][k] = lo(Wvo[k][n])
__device__ float g_z[(size_t)M_TOT * CC];   // pre-LN activations (16.8 MB)
__device__ float g_psum[256 * CC];          // per-(64-row warp-tile) column sums
__device__ float g_psq [256 * CC];
__device__ float g_mean[BB * CC];
__device__ float g_inv[BB * CC];            // rsqrt(var + eps)

// ---------------------------------------------------------------------------
// Warp-MMA helpers (plain sm_80-era PTX: compiles at compute_103)
// ---------------------------------------------------------------------------
__device__ __forceinline__ uint32_t smem_u32(const void* p) {
    uint32_t a;
    asm("{ .reg .u64 t; cvta.to.shared.u64 t, %1; cvt.u32.u64 %0, t; }" : "=r"(a) : "l"(p));
    return a;
}

#define LDMX4(r, a) \
    asm volatile("ldmatrix.sync.aligned.m8n8.x4.shared.b16 {%0,%1,%2,%3}, [%4];" \
        : "=r"((r)[0]), "=r"((r)[1]), "=r"((r)[2]), "=r"((r)[3]) : "r"(a))
#define LDMX2(r, a) \
    asm volatile("ldmatrix.sync.aligned.m8n8.x2.shared.b16 {%0,%1}, [%2];" \
        : "=r"((r)[0]), "=r"((r)[1]) : "r"(a))
#define MMA16816(c, a, b) \
    asm volatile("mma.sync.aligned.m16n8k16.row.col.f32.bf16.bf16.f32 " \
        "{%0,%1,%2,%3}, {%4,%5,%6,%7}, {%8,%9}, {%0,%1,%2,%3};" \
        : "+f"((c)[0]), "+f"((c)[1]), "+f"((c)[2]), "+f"((c)[3]) \
        : "r"((a)[0]), "r"((a)[1]), "r"((a)[2]), "r"((a)[3]), "r"((b)[0]), "r"((b)[1]))

// Split 8 fp32 into hi/lo bf16, packed 8 x bf16 per uint4.
__device__ __forceinline__ void split8(float4 a, float4 b, uint4& hi, uint4& lo) {
    float f[8] = {a.x, a.y, a.z, a.w, b.x, b.y, b.z, b.w};
    uint32_t h[8], l[8];
#pragma unroll
    for (int j = 0; j < 8; ++j) {
        __nv_bfloat16 bh = __float2bfloat16_rn(f[j]);
        float r = f[j] - __bfloat162float(bh);
        __nv_bfloat16 bl = __float2bfloat16_rn(r);
        h[j] = (uint32_t)__bfloat16_as_ushort(bh);
        l[j] = (uint32_t)__bfloat16_as_ushort(bl);
    }
    hi = make_uint4(h[0] | (h[1] << 16), h[2] | (h[3] << 16), h[4] | (h[5] << 16), h[6] | (h[7] << 16));
    lo = make_uint4(l[0] | (l[1] << 16), l[2] | (l[3] << 16), l[4] | (l[5] << 16), l[6] | (l[7] << 16));
}

// ---------------------------------------------------------------------------
// Kernel 1: fold weights Wvo = Wv @ Wo, split bf16 hi/lo, store TRANSPOSED
// [n][k] (K-major) = col-major B operand for mma.row.col. Biases cancel in
// the points-axis LayerNorm and are dead.
// ---------------------------------------------------------------------------
__global__ void k_prep(const float* __restrict__ Wv, const float* __restrict__ Wo) {
    const int i = blockIdx.x;     // k index (row of Wvo)
    const int j = threadIdx.x;    // n index (col of Wvo)
    float acc = 0.f;
#pragma unroll 8
    for (int m = 0; m < CC; ++m)
        acc += Wv[i * CC + m] * Wo[m * CC + j];
    __nv_bfloat16 h = __float2bfloat16_rn(acc);
    float r = acc - __bfloat162float(h);
    g_BhT[j * CC + i] = h;
    g_BlT[j * CC + i] = __float2bfloat16_rn(r);
}

// ---------------------------------------------------------------------------
// Kernel 2: bf16-split warp-MMA GEMM  z = X[16384,256] @ Wvo[256,256]
// 128 CTAs x 256 thr. CTA tile 128m x 256n; warp tile 64x64 (2m x 4n warps).
// K in 4 chunks of 64. Passes AhBh + AlBh + AhBl accumulate fp32 fragments.
// Fused deterministic per-warp column stats (sum/sumsq over 64 rows).
// smem: AH 16K | AL 16K | BH 32K | BL 32K = 96KB (SW128-swizzled 128B rows).
// ---------------------------------------------------------------------------
#define SM_AH 0
#define SM_AL 16384
#define SM_BH 32768
#define SM_BL 65536
#define SMEM_TOTAL 98304

__global__ void __launch_bounds__(256, 1)
k_gemm_mma(const float* __restrict__ X) {
    extern __shared__ char smem[];
    const uint32_t sb = smem_u32(smem);
    const int tid = threadIdx.x;
    const int lane = tid & 31;
    const int warp = tid >> 5;
    const int warp_m = warp & 1;       // 2 warps along m (64 each)
    const int warp_n = warp >> 1;      // 4 warps along n (64 each)
    const int rowBase = blockIdx.x * 128;

    float c[4][8][4];
#pragma unroll
    for (int mi = 0; mi < 4; ++mi)
#pragma unroll
        for (int ni = 0; ni < 8; ++ni)
#pragma unroll
            for (int e = 0; e < 4; ++e) c[mi][ni][e] = 0.f;

    // Precompute ldmatrix addresses (swizzled) — loop-invariant parts
    const int arow = warp_m * 64 + (lane & 15);
    const uint32_t acb = (uint32_t)((lane >> 4) << 4);          // 0 or 16 bytes
    const int brow0 = warp_n * 64 + (lane & 7);
    const uint32_t bcb = (uint32_t)(((lane >> 3) & 1) << 4);    // 0 or 16 bytes

    for (int kc = 0; kc < 4; ++kc) {
        // ---- load + split A chunk: 128 rows x 64 k (fp32 -> bf16 hi/lo) ----
        {
            const int row = tid >> 1;
            const int ch = (tid & 1) * 32;
            const float4* xr = (const float4*)(X + (size_t)(rowBase + row) * CC + kc * 64 + ch);
#pragma unroll
            for (int g = 0; g < 4; ++g) {
                float4 a = xr[2 * g], b = xr[2 * g + 1];
                uint4 hi, lo;
                split8(a, b, hi, lo);
                uint32_t off = (uint32_t)(row * 128 + (ch + g * 8) * 2);
                uint32_t sw = off ^ (((uint32_t)(row & 7)) << 4);
                *(uint4*)(smem + SM_AH + sw) = hi;
                *(uint4*)(smem + SM_AL + sw) = lo;
            }
        }
        // ---- load B chunk (pre-split bf16): 256 n-rows x 64 k ----
        {
            const int n = tid;
            const uint4* bh = (const uint4*)(g_BhT + (size_t)n * CC + kc * 64);
            const uint4* bl = (const uint4*)(g_BlT + (size_t)n * CC + kc * 64);
#pragma unroll
            for (int g = 0; g < 8; ++g) {
                uint32_t off = (uint32_t)(n * 128 + g * 16);
                uint32_t sw = off ^ (((uint32_t)(n & 7)) << 4);
                *(uint4*)(smem + SM_BH + sw) = bh[g];
                *(uint4*)(smem + SM_BL + sw) = bl[g];
            }
        }
        __syncthreads();

#pragma unroll
        for (int ks = 0; ks < 4; ++ks) {
            const uint32_t kbyte = (uint32_t)(ks * 32);
            uint32_t ah[4][4], al[4][4];
#pragma unroll
            for (int mi = 0; mi < 4; ++mi) {
                const int r = arow + mi * 16;
                uint32_t sw = ((uint32_t)(r * 128) + kbyte + acb) ^ (((uint32_t)(r & 7)) << 4);
                LDMX4(ah[mi], sb + SM_AH + sw);
                LDMX4(al[mi], sb + SM_AL + sw);
            }
            uint32_t b[8][2];
#pragma unroll
            for (int ni = 0; ni < 8; ++ni) {
                const int r = brow0 + ni * 8;
                uint32_t sw = ((uint32_t)(r * 128) + kbyte + bcb) ^ (((uint32_t)(r & 7)) << 4);
                LDMX2(b[ni], sb + SM_BH + sw);
            }
#pragma unroll
            for (int mi = 0; mi < 4; ++mi)
#pragma unroll
                for (int ni = 0; ni < 8; ++ni)
                    MMA16816(c[mi][ni], ah[mi], b[ni]);
#pragma unroll
            for (int mi = 0; mi < 4; ++mi)
#pragma unroll
                for (int ni = 0; ni < 8; ++ni)
                    MMA16816(c[mi][ni], al[mi], b[ni]);
            // reload B <- lo half, then Ah*Bl
#pragma unroll
            for (int ni = 0; ni < 8; ++ni) {
                const int r = brow0 + ni * 8;
                uint32_t sw = ((uint32_t)(r * 128) + kbyte + bcb) ^ (((uint32_t)(r & 7)) << 4);
                LDMX2(b[ni], sb + SM_BL + sw);
            }
#pragma unroll
            for (int mi = 0; mi < 4; ++mi)
#pragma unroll
                for (int ni = 0; ni < 8; ++ni)
                    MMA16816(c[mi][ni], ah[mi], b[ni]);
        }
        __syncthreads();
    }

    // ---- epilogue: store z + deterministic fused column stats ----
    // C frag mapping: thread holds (r, r+8) x (q, q+1); r = lane/4, q = 2*(lane%4)
    const int gr = lane >> 2;
    const int qc = (lane & 3) * 2;
    const int mW = rowBase + warp_m * 64;
    const int nW = warp_n * 64;
    const int prow = blockIdx.x * 2 + warp_m;

#pragma unroll
    for (int ni = 0; ni < 8; ++ni) {
        float s0 = 0.f, s1 = 0.f, q0 = 0.f, q1 = 0.f;
        const int n0 = nW + ni * 8 + qc;
#pragma unroll
        for (int mi = 0; mi < 4; ++mi) {
            const float* cf = c[mi][ni];
            const int m0 = mW + mi * 16 + gr;
            *(float2*)(g_z + (size_t)m0 * CC + n0)       = make_float2(cf[0], cf[1]);
            *(float2*)(g_z + (size_t)(m0 + 8) * CC + n0) = make_float2(cf[2], cf[3]);
            s0 += cf[0] + cf[2];
            s1 += cf[1] + cf[3];
            q0 += cf[0] * cf[0] + cf[2] * cf[2];
            q1 += cf[1] * cf[1] + cf[3] * cf[3];
        }
#pragma unroll
        for (int off = 4; off < 32; off <<= 1) {
            s0 += __shfl_xor_sync(0xFFFFFFFFu, s0, off);
            s1 += __shfl_xor_sync(0xFFFFFFFFu, s1, off);
            q0 += __shfl_xor_sync(0xFFFFFFFFu, q0, off);
            q1 += __shfl_xor_sync(0xFFFFFFFFu, q1, off);
        }
        if (lane < 4) {
            g_psum[prow * CC + n0]     = s0;
            g_psum[prow * CC + n0 + 1] = s1;
            g_psq [prow * CC + n0]     = q0;
            g_psq [prow * CC + n0 + 1] = q1;
        }
    }
}

// ---------------------------------------------------------------------------
// Kernel 3: finalize mean / inv-std per (batch, channel) from 64 partials
// ---------------------------------------------------------------------------
__global__ void k_finalize() {
    const int b = blockIdx.x;
    const int c = threadIdx.x;
    float s = 0.f, s2 = 0.f;
#pragma unroll 8
    for (int p = 0; p < 64; ++p) {
        s  += g_psum[(b * 64 + p) * CC + c];
        s2 += g_psq [(b * 64 + p) * CC + c];
    }
    const float mean = s * (1.f / NN);
    const float var  = s2 * (1.f / NN) - mean * mean;
    g_mean[b * CC + c] = mean;
    g_inv [b * CC + c] = rsqrtf(var + LN_EPS);
}

// ---------------------------------------------------------------------------
// Kernel 4: epilogue  out = relu((z-mean)*inv*scale + bias) + x
// ---------------------------------------------------------------------------
__global__ void __launch_bounds__(256)
k_epi(const float* __restrict__ X, const float* __restrict__ scale,
      const float* __restrict__ bias, float* __restrict__ out) {
    const int idx = blockIdx.x * blockDim.x + threadIdx.x;   // float4 index
    const int c4  = idx & 63;
    const int row = idx >> 6;
    const int b   = row >> 12;

    float4 z  = ((const float4*)g_z)[idx];
    float4 x  = ((const float4*)X)[idx];
    float4 mn = ((const float4*)(g_mean + b * CC))[c4];
    float4 iv = ((const float4*)(g_inv  + b * CC))[c4];
    float4 sc = ((const float4*)scale)[c4];
    float4 bi = ((const float4*)bias)[c4];

    float4 o;
    o.x = fmaxf((z.x - mn.x) * iv.x * sc.x + bi.x, 0.f) + x.x;
    o.y = fmaxf((z.y - mn.y) * iv.y * sc.y + bi.y, 0.f) + x.y;
    o.z = fmaxf((z.z - mn.z) * iv.z * sc.z + bi.z, 0.f) + x.z;
    o.w = fmaxf((z.w - mn.w) * iv.w * sc.w + bi.w, 0.f) + x.w;
    ((float4*)out)[idx] = o;
}

// ---------------------------------------------------------------------------
// Inputs: 0=inputs 1=mask 2=Wq 3=bq 4=Wk 5=bk 6=Wv 7=bv 8=Wo 9=bo
//         10=ln_scale 11=ln_bias
// mask/Wq/bq/Wk/bk numerically irrelevant (softmax column-sum collapse);
// bv/bo cancel in the points-axis LayerNorm. All dead.
// ---------------------------------------------------------------------------
extern "C" void kernel_launch(void* const* d_in, const int* in_sizes, int n_in,
                              void* d_out, int out_size) {
    const float* x        = (const float*)d_in[0];
    const float* Wv       = (const float*)d_in[6];
    const float* Wo       = (const float*)d_in[8];
    const float* ln_scale = (const float*)d_in[10];
    const float* ln_bias  = (const float*)d_in[11];
    float* out = (float*)d_out;

    cudaFuncSetAttribute(k_gemm_mma, cudaFuncAttributeMaxDynamicSharedMemorySize, SMEM_TOTAL);

    k_prep<<<CC, CC>>>(Wv, Wo);
    k_gemm_mma<<<M_TOT / 128, 256, SMEM_TOTAL>>>(x);
    k_finalize<<<BB, CC>>>();
    k_epi<<<(M_TOT * CC / 4) / 256, 256>>>(x, ln_scale, ln_bias, out);
}

// round 5
// speedup vs baseline: 2.1743x; 1.0407x over previous
#include <cuda_runtime.h>
#include <cuda_bf16.h>
#include <cstdint>

// Problem constants (fixed by the reference: B=4, N=4096, C=256)
#define BB 4
#define NN 4096
#define CC 256
#define M_TOT (BB * NN)          // 16384 rows
#define LN_EPS 1e-6f

// ---------------------------------------------------------------------------
// Scratch (static device globals; no runtime allocation allowed)
// ---------------------------------------------------------------------------
__device__ __align__(16) __nv_bfloat16 g_BhT[CC * CC]; // [n][k] = hi(Wvo[k][n])
__device__ __align__(16) __nv_bfloat16 g_BlT[CC * CC]; // [n][k] = lo(Wvo[k][n])
__device__ float g_z[(size_t)M_TOT * CC];   // pre-LN activations (16.8 MB)
__device__ float g_psum[256 * CC];          // per-(64-row warp-tile) column sums
__device__ float g_psq [256 * CC];
__device__ float g_mean[BB * CC];
__device__ float g_inv[BB * CC];            // rsqrt(var + eps)

// ---------------------------------------------------------------------------
// Warp-MMA + cp.async helpers (sm_80-era PTX: compiles at compute_103)
// ---------------------------------------------------------------------------
__device__ __forceinline__ uint32_t smem_u32(const void* p) {
    uint32_t a;
    asm("{ .reg .u64 t; cvta.to.shared.u64 t, %1; cvt.u32.u64 %0, t; }" : "=r"(a) : "l"(p));
    return a;
}
#define LDMX4(r, a) \
    asm volatile("ldmatrix.sync.aligned.m8n8.x4.shared.b16 {%0,%1,%2,%3}, [%4];" \
        : "=r"((r)[0]), "=r"((r)[1]), "=r"((r)[2]), "=r"((r)[3]) : "r"(a))
#define LDMX2(r, a) \
    asm volatile("ldmatrix.sync.aligned.m8n8.x2.shared.b16 {%0,%1}, [%2];" \
        : "=r"((r)[0]), "=r"((r)[1]) : "r"(a))
#define MMA16816(c, a, b) \
    asm volatile("mma.sync.aligned.m16n8k16.row.col.f32.bf16.bf16.f32 " \
        "{%0,%1,%2,%3}, {%4,%5,%6,%7}, {%8,%9}, {%0,%1,%2,%3};" \
        : "+f"((c)[0]), "+f"((c)[1]), "+f"((c)[2]), "+f"((c)[3]) \
        : "r"((a)[0]), "r"((a)[1]), "r"((a)[2]), "r"((a)[3]), "r"((b)[0]), "r"((b)[1]))
#define CP16(dst, src) \
    asm volatile("cp.async.cg.shared.global [%0], [%1], 16;" :: "r"(dst), "l"(src))
#define CP_COMMIT() asm volatile("cp.async.commit_group;" ::: "memory")
#define CP_WAIT(n)  asm volatile("cp.async.wait_group %0;" :: "n"(n) : "memory")

// Split 8 fp32 into hi/lo bf16, packed 8 x bf16 per uint4.
__device__ __forceinline__ void split8(float4 a, float4 b, uint4& hi, uint4& lo) {
    float f[8] = {a.x, a.y, a.z, a.w, b.x, b.y, b.z, b.w};
    uint32_t h[8], l[8];
#pragma unroll
    for (int j = 0; j < 8; ++j) {
        __nv_bfloat16 bh = __float2bfloat16_rn(f[j]);
        float r = f[j] - __bfloat162float(bh);
        __nv_bfloat16 bl = __float2bfloat16_rn(r);
        h[j] = (uint32_t)__bfloat16_as_ushort(bh);
        l[j] = (uint32_t)__bfloat16_as_ushort(bl);
    }
    hi = make_uint4(h[0] | (h[1] << 16), h[2] | (h[3] << 16), h[4] | (h[5] << 16), h[6] | (h[7] << 16));
    lo = make_uint4(l[0] | (l[1] << 16), l[2] | (l[3] << 16), l[4] | (l[5] << 16), l[6] | (l[7] << 16));
}

// ---------------------------------------------------------------------------
// Kernel 1: fold weights Wvo = Wv @ Wo, split bf16 hi/lo, store TRANSPOSED
// [n][k] (K-major). Biases cancel in the points-axis LayerNorm (dead).
// ---------------------------------------------------------------------------
__global__ void k_prep(const float* __restrict__ Wv, const float* __restrict__ Wo) {
    const int i = blockIdx.x;     // k index (row of Wvo)
    const int j = threadIdx.x;    // n index (col of Wvo)
    float acc = 0.f;
#pragma unroll 8
    for (int m = 0; m < CC; ++m)
        acc += Wv[i * CC + m] * Wo[m * CC + j];
    __nv_bfloat16 h = __float2bfloat16_rn(acc);
    float r = acc - __bfloat162float(h);
    g_BhT[j * CC + i] = h;
    g_BlT[j * CC + i] = __float2bfloat16_rn(r);
}

// ---------------------------------------------------------------------------
// Kernel 2: bf16-split warp-MMA GEMM  z = X[16384,256] @ Wvo[256,256]
// 128 CTAs x 256 thr; CTA tile 128m x 256n; warp tile 64x64.
// K in 4 chunks of 64, DOUBLE-BUFFERED:
//   - B(hi/lo) streamed via cp.async into the idle stage during compute
//   - next A chunk LDG'd (fp32) into registers during compute; split->STS in
//     the short inter-chunk window
// Passes AhBh + AlBh + AhBl accumulate fp32 fragments. Fused per-warp
// deterministic column stats. smem = 2 stages x (A 32K + B 64K) = 192 KB.
// ---------------------------------------------------------------------------
#define SM_AH(s) ((s) * 32768)
#define SM_AL(s) ((s) * 32768 + 16384)
#define SM_BH(s) (65536 + (s) * 65536)
#define SM_BL(s) (65536 + (s) * 65536 + 32768)
#define SMEM_TOTAL 196608

__global__ void __launch_bounds__(256, 1)
k_gemm_mma(const float* __restrict__ X) {
    extern __shared__ char smem[];
    const uint32_t sb = smem_u32(smem);
    const int tid = threadIdx.x;
    const int lane = tid & 31;
    const int warp = tid >> 5;
    const int warp_m = warp & 1;       // 2 warps along m (64 each)
    const int warp_n = warp >> 1;      // 4 warps along n (64 each)
    const int rowBase = blockIdx.x * 128;

    // A-load mapping: 2 threads per row, 32 fp32 each (8 float4)
    const int a_ldrow = tid >> 1;
    const int a_ldch  = (tid & 1) * 32;

    float c[4][8][4];
#pragma unroll
    for (int mi = 0; mi < 4; ++mi)
#pragma unroll
        for (int ni = 0; ni < 8; ++ni)
#pragma unroll
            for (int e = 0; e < 4; ++e) c[mi][ni][e] = 0.f;

    // ---- helpers as lambdas ----
    auto loadB = [&](int stage, int kc) {
        const char* bh = (const char*)g_BhT + (size_t)tid * 512 + kc * 128;
        const char* bl = (const char*)g_BlT + (size_t)tid * 512 + kc * 128;
        const uint32_t rsw = ((uint32_t)(tid & 7)) << 4;
#pragma unroll
        for (int g = 0; g < 8; ++g) {
            uint32_t sw = ((uint32_t)(tid * 128 + g * 16)) ^ rsw;
            CP16(sb + SM_BH(stage) + sw, bh + g * 16);
            CP16(sb + SM_BL(stage) + sw, bl + g * 16);
        }
        CP_COMMIT();
    };
    auto loadAreg = [&](int kc, float4* xr) {
        const float4* xp = (const float4*)(X + (size_t)(rowBase + a_ldrow) * CC + kc * 64 + a_ldch);
#pragma unroll
        for (int g = 0; g < 8; ++g) xr[g] = xp[g];
    };
    auto splitA = [&](int stage, const float4* xr) {
        const uint32_t rsw = ((uint32_t)(a_ldrow & 7)) << 4;
#pragma unroll
        for (int g = 0; g < 4; ++g) {
            uint4 hi, lo;
            split8(xr[2 * g], xr[2 * g + 1], hi, lo);
            uint32_t sw = ((uint32_t)(a_ldrow * 128 + (a_ldch + g * 8) * 2)) ^ rsw;
            *(uint4*)(smem + SM_AH(stage) + sw) = hi;
            *(uint4*)(smem + SM_AL(stage) + sw) = lo;
        }
    };

    // ---- prologue: B0,B1 in flight; A0 split to smem; A1 in regs ----
    float4 xr[8];
    loadB(0, 0);
    loadB(1, 1);
    loadAreg(0, xr);
    splitA(0, xr);
    loadAreg(1, xr);
    CP_WAIT(1);            // B0 arrived
    __syncthreads();

    // ldmatrix address components
    const int arow = warp_m * 64 + (lane & 15);
    const uint32_t acb = (uint32_t)((lane >> 4) << 4);
    const int brow0 = warp_n * 64 + (lane & 7);
    const uint32_t bcb = (uint32_t)(((lane >> 3) & 1) << 4);

#pragma unroll
    for (int kc = 0; kc < 4; ++kc) {
        const int s = kc & 1;
        const uint32_t AH = sb + SM_AH(s), AL = sb + SM_AL(s);
        const uint32_t BH = sb + SM_BH(s), BL = sb + SM_BL(s);

#pragma unroll
        for (int ks = 0; ks < 4; ++ks) {
            const uint32_t kbyte = (uint32_t)(ks * 32);
            uint32_t ah[4][4], al[4][4];
#pragma unroll
            for (int mi = 0; mi < 4; ++mi) {
                const int r = arow + mi * 16;
                uint32_t sw = ((uint32_t)(r * 128) + kbyte + acb) ^ (((uint32_t)(r & 7)) << 4);
                LDMX4(ah[mi], AH + sw);
                LDMX4(al[mi], AL + sw);
            }
            uint32_t b[8][2];
#pragma unroll
            for (int ni = 0; ni < 8; ++ni) {
                const int r = brow0 + ni * 8;
                uint32_t sw = ((uint32_t)(r * 128) + kbyte + bcb) ^ (((uint32_t)(r & 7)) << 4);
                LDMX2(b[ni], BH + sw);
            }
#pragma unroll
            for (int mi = 0; mi < 4; ++mi)
#pragma unroll
                for (int ni = 0; ni < 8; ++ni)
                    MMA16816(c[mi][ni], ah[mi], b[ni]);
#pragma unroll
            for (int mi = 0; mi < 4; ++mi)
#pragma unroll
                for (int ni = 0; ni < 8; ++ni)
                    MMA16816(c[mi][ni], al[mi], b[ni]);
#pragma unroll
            for (int ni = 0; ni < 8; ++ni) {
                const int r = brow0 + ni * 8;
                uint32_t sw = ((uint32_t)(r * 128) + kbyte + bcb) ^ (((uint32_t)(r & 7)) << 4);
                LDMX2(b[ni], BL + sw);
            }
#pragma unroll
            for (int mi = 0; mi < 4; ++mi)
#pragma unroll
                for (int ni = 0; ni < 8; ++ni)
                    MMA16816(c[mi][ni], ah[mi], b[ni]);
        }

        if (kc < 3) {
            __syncthreads();                 // all warps done reading stage s
            if (kc < 2) loadB(s, kc + 2);    // refill just-freed B stage
            splitA(s ^ 1, xr);               // A(kc+1) regs -> smem
            if (kc < 2) loadAreg(kc + 2, xr);
            if (kc < 2) { CP_WAIT(1); } else { CP_WAIT(0); }  // B(kc+1) arrived
            __syncthreads();
        }
    }

    // ---- epilogue: store z + deterministic fused column stats ----
    const int gr = lane >> 2;
    const int qc = (lane & 3) * 2;
    const int mW = rowBase + warp_m * 64;
    const int nW = warp_n * 64;
    const int prow = blockIdx.x * 2 + warp_m;

#pragma unroll
    for (int ni = 0; ni < 8; ++ni) {
        float s0 = 0.f, s1 = 0.f, q0 = 0.f, q1 = 0.f;
        const int n0 = nW + ni * 8 + qc;
#pragma unroll
        for (int mi = 0; mi < 4; ++mi) {
            const float* cf = c[mi][ni];
            const int m0 = mW + mi * 16 + gr;
            *(float2*)(g_z + (size_t)m0 * CC + n0)       = make_float2(cf[0], cf[1]);
            *(float2*)(g_z + (size_t)(m0 + 8) * CC + n0) = make_float2(cf[2], cf[3]);
            s0 += cf[0] + cf[2];
            s1 += cf[1] + cf[3];
            q0 += cf[0] * cf[0] + cf[2] * cf[2];
            q1 += cf[1] * cf[1] + cf[3] * cf[3];
        }
#pragma unroll
        for (int off = 4; off < 32; off <<= 1) {
            s0 += __shfl_xor_sync(0xFFFFFFFFu, s0, off);
            s1 += __shfl_xor_sync(0xFFFFFFFFu, s1, off);
            q0 += __shfl_xor_sync(0xFFFFFFFFu, q0, off);
            q1 += __shfl_xor_sync(0xFFFFFFFFu, q1, off);
        }
        if (lane < 4) {
            g_psum[prow * CC + n0]     = s0;
            g_psum[prow * CC + n0 + 1] = s1;
            g_psq [prow * CC + n0]     = q0;
            g_psq [prow * CC + n0 + 1] = q1;
        }
    }
}

// ---------------------------------------------------------------------------
// Kernel 3: finalize mean / inv-std per (batch, channel) from 64 partials
// ---------------------------------------------------------------------------
__global__ void k_finalize() {
    const int b = blockIdx.x;
    const int c = threadIdx.x;
    float s = 0.f, s2 = 0.f;
#pragma unroll 8
    for (int p = 0; p < 64; ++p) {
        s  += g_psum[(b * 64 + p) * CC + c];
        s2 += g_psq [(b * 64 + p) * CC + c];
    }
    const float mean = s * (1.f / NN);
    const float var  = s2 * (1.f / NN) - mean * mean;
    g_mean[b * CC + c] = mean;
    g_inv [b * CC + c] = rsqrtf(var + LN_EPS);
}

// ---------------------------------------------------------------------------
// Kernel 4: epilogue  out = relu((z-mean)*inv*scale + bias) + x
// Grid-stride (512 blocks x 8 iters) for MLP depth + less tail quantization.
// ---------------------------------------------------------------------------
__global__ void __launch_bounds__(256)
k_epi(const float* __restrict__ X, const float* __restrict__ scale,
      const float* __restrict__ bias, float* __restrict__ out) {
    const int total  = M_TOT * CC / 4;
    const int stride = gridDim.x * blockDim.x;
#pragma unroll 4
    for (int idx = blockIdx.x * blockDim.x + threadIdx.x; idx < total; idx += stride) {
        const int c4  = idx & 63;
        const int row = idx >> 6;
        const int b   = row >> 12;

        float4 z  = ((const float4*)g_z)[idx];
        float4 x  = ((const float4*)X)[idx];
        float4 mn = ((const float4*)(g_mean + b * CC))[c4];
        float4 iv = ((const float4*)(g_inv  + b * CC))[c4];
        float4 sc = ((const float4*)scale)[c4];
        float4 bi = ((const float4*)bias)[c4];

        float4 o;
        o.x = fmaxf((z.x - mn.x) * iv.x * sc.x + bi.x, 0.f) + x.x;
        o.y = fmaxf((z.y - mn.y) * iv.y * sc.y + bi.y, 0.f) + x.y;
        o.z = fmaxf((z.z - mn.z) * iv.z * sc.z + bi.z, 0.f) + x.z;
        o.w = fmaxf((z.w - mn.w) * iv.w * sc.w + bi.w, 0.f) + x.w;
        ((float4*)out)[idx] = o;
    }
}

// ---------------------------------------------------------------------------
// Inputs: 0=inputs 1=mask 2=Wq 3=bq 4=Wk 5=bk 6=Wv 7=bv 8=Wo 9=bo
//         10=ln_scale 11=ln_bias
// mask/Wq/bq/Wk/bk numerically irrelevant (softmax column-sum collapse);
// bv/bo cancel in the points-axis LayerNorm. All dead.
// ---------------------------------------------------------------------------
extern "C" void kernel_launch(void* const* d_in, const int* in_sizes, int n_in,
                              void* d_out, int out_size) {
    const float* x        = (const float*)d_in[0];
    const float* Wv       = (const float*)d_in[6];
    const float* Wo       = (const float*)d_in[8];
    const float* ln_scale = (const float*)d_in[10];
    const float* ln_bias  = (const float*)d_in[11];
    float* out = (float*)d_out;

    cudaFuncSetAttribute(k_gemm_mma, cudaFuncAttributeMaxDynamicSharedMemorySize, SMEM_TOTAL);

    k_prep<<<CC, CC>>>(Wv, Wo);
    k_gemm_mma<<<M_TOT / 128, 256, SMEM_TOTAL>>>(x);
    k_finalize<<<BB, CC>>>();
    k_epi<<<512, 256>>>(x, ln_scale, ln_bias, out);
}